// round 1
// baseline (speedup 1.0000x reference)
#include <cuda_runtime.h>

// out = outer(w, x) @ x0 + bias + x  ==  w * dot(x, x0) + bias + x
// D = 8192. Inputs (metadata order): x0, x, weight, bias. Output: float32[8192].

#define D 8192
#define NBLK 16
#define NTHR 128   // 16 blocks * 128 threads = 2048 threads = 2048 float4 = 8192 floats

__device__ float g_partials[NBLK];

// Kernel 1: per-block partial dot(x, x0)
__global__ void __launch_bounds__(NTHR) cross_dot_kernel(const float4* __restrict__ x0,
                                                         const float4* __restrict__ x) {
    int i = blockIdx.x * NTHR + threadIdx.x;
    float4 a = x0[i];
    float4 b = x[i];
    float s = a.x * b.x + a.y * b.y + a.z * b.z + a.w * b.w;

    // warp reduction
    #pragma unroll
    for (int o = 16; o > 0; o >>= 1)
        s += __shfl_xor_sync(0xFFFFFFFFu, s, o);

    __shared__ float ws[NTHR / 32];
    if ((threadIdx.x & 31) == 0) ws[threadIdx.x >> 5] = s;
    __syncthreads();
    if (threadIdx.x == 0) {
        float t = 0.f;
        #pragma unroll
        for (int w = 0; w < NTHR / 32; w++) t += ws[w];
        g_partials[blockIdx.x] = t;
    }
}

// Kernel 2: s = sum(partials); out = w*s + bias + x
__global__ void __launch_bounds__(NTHR) cross_out_kernel(const float4* __restrict__ x,
                                                         const float4* __restrict__ w,
                                                         const float4* __restrict__ b,
                                                         float4* __restrict__ out) {
    float s = 0.f;
    #pragma unroll
    for (int k = 0; k < NBLK; k++) s += g_partials[k];

    int i = blockIdx.x * NTHR + threadIdx.x;
    float4 xv = x[i];
    float4 wv = w[i];
    float4 bv = b[i];
    float4 o;
    o.x = fmaf(wv.x, s, bv.x + xv.x);
    o.y = fmaf(wv.y, s, bv.y + xv.y);
    o.z = fmaf(wv.z, s, bv.z + xv.z);
    o.w = fmaf(wv.w, s, bv.w + xv.w);
    out[i] = o;
}

extern "C" void kernel_launch(void* const* d_in, const int* in_sizes, int n_in,
                              void* d_out, int out_size) {
    const float4* x0 = (const float4*)d_in[0];
    const float4* x  = (const float4*)d_in[1];
    const float4* w  = (const float4*)d_in[2];
    const float4* b  = (const float4*)d_in[3];
    float4* out = (float4*)d_out;

    cross_dot_kernel<<<NBLK, NTHR>>>(x0, x);
    cross_out_kernel<<<NBLK, NTHR>>>(x, w, b, out);
}